// round 1
// baseline (speedup 1.0000x reference)
#include <cuda_runtime.h>
#include <cstdint>
#include <cstddef>

// Problem constants
#define B_   16
#define CI_  32
#define HH   224
#define WW   224
#define CO_  32
#define OHh  222
#define OWw  222

// Tiling
#define TW      64          // output tile width per CTA
#define TH      8           // output tile height per CTA
#define XT      4           // ceil(222/64)
#define YT      28          // ceil(222/8)
#define THREADS 512

#define IN_ROWS   (TH + 2)                 // 10 input rows per tile
#define IN_STRIDE 68                       // TW+2 halo, padded to mult of 4 for float4
#define SIN_FLOATS (CI_ * IN_ROWS * IN_STRIDE)   // 21760
#define SW_FLOATS  (CI_ * 9 * 64)                // 18432 (weights duplicated per-co pair)
#define SMEM_BYTES ((SIN_FLOATS + SW_FLOATS) * 4)

typedef unsigned long long ull;

// Packed fp32x2 helpers (sm_100+ packed-f32 pipe; 2 MACs per FFMA2 instruction)
__device__ __forceinline__ ull pk2(float a, float b) {
    ull r;
    asm("mov.b64 %0, {%1, %2};" : "=l"(r) : "f"(a), "f"(b));
    return r;
}
__device__ __forceinline__ void fma2(ull& d, ull a, ull b) {
    asm("fma.rn.f32x2 %0, %1, %2, %0;" : "+l"(d) : "l"(a), "l"(b));
}
__device__ __forceinline__ void unpk2(ull v, float& lo, float& hi) {
    asm("mov.b64 {%0, %1}, %2;" : "=f"(lo), "=f"(hi) : "l"(v));
}

__global__ void __launch_bounds__(THREADS, 1)
conv3x3_f32x2(const float* __restrict__ x,
              const float* __restrict__ w,
              const float* __restrict__ bias,
              float* __restrict__ out)
{
    extern __shared__ float smem[];
    float* sIn = smem;                // [ci][10][68]
    float* sW  = smem + SIN_FLOATS;   // [ci][tap][co dup-pair: 64 floats]

    const int tid = threadIdx.x;
    const int bid = blockIdx.x;
    const int bx  = bid & 3;               // XT = 4
    const int by  = (bid >> 2) % YT;
    const int b   = bid / (4 * YT);
    const int ow0 = bx * TW;
    const int oh0 = by * TH;

    // ---- load weights into smem, each weight duplicated into an adjacent pair
    // global w layout: [co][ci][ky][kx] -> i = co*288 + ci*9 + tap
    // smem layout: sW[(ci*9 + tap)*64 + co*2 + {0,1}]
    #pragma unroll 1
    for (int i = tid; i < CO_ * CI_ * 9; i += THREADS) {
        int co = i / (CI_ * 9);
        int r  = i - co * (CI_ * 9);        // ci*9 + tap
        float v = w[i];
        int o = r * 64 + co * 2;
        sW[o]     = v;
        sW[o + 1] = v;
    }

    // ---- load input tile (zero-fill out-of-range)
    const float* xb = x + (size_t)b * CI_ * HH * WW;
    #pragma unroll 1
    for (int i = tid; i < SIN_FLOATS; i += THREADS) {
        int c  = i % IN_STRIDE;
        int t  = i / IN_STRIDE;
        int r  = t % IN_ROWS;
        int ci = t / IN_ROWS;
        int ih = oh0 + r;
        int iw = ow0 + c;
        float v = 0.f;
        if (ih < HH && iw < WW) v = __ldg(&xb[ci * HH * WW + ih * WW + iw]);
        sIn[i] = v;
    }
    __syncthreads();

    // ---- per-thread work: 4 consecutive co  x  8 consecutive pixels (as 4 f32x2 pairs)
    const int cog  = tid >> 6;        // 0..7  -> co = cog*4 .. cog*4+3
    const int slot = tid & 63;        // 0..63
    const int py   = slot >> 3;       // 0..7
    const int px   = (slot & 7) << 3; // 0,8,...,56

    ull acc[16];
    #pragma unroll
    for (int i = 0; i < 16; i++) acc[i] = 0ULL;

    const float* inb = &sIn[py * IN_STRIDE + px];
    const float* wb  = &sW[cog * 8];

    #pragma unroll 1
    for (int ci = 0; ci < CI_; ++ci) {
        const float* rbase = inb + ci * IN_ROWS * IN_STRIDE;
        const float* wci   = wb + ci * 9 * 64;
        #pragma unroll
        for (int ky = 0; ky < 3; ++ky) {
            const float4* rp = (const float4*)(rbase + ky * IN_STRIDE);
            float4 A = rp[0], Bv = rp[1], Cv = rp[2];
            float vv[12] = {A.x, A.y, A.z, A.w,
                            Bv.x, Bv.y, Bv.z, Bv.w,
                            Cv.x, Cv.y, Cv.z, Cv.w};
            ull p[9];
            #pragma unroll
            for (int s = 0; s < 9; s++) p[s] = pk2(vv[s], vv[s + 1]);

            #pragma unroll
            for (int kx = 0; kx < 3; ++kx) {
                const ulonglong2* wp = (const ulonglong2*)(wci + (ky * 3 + kx) * 64);
                ulonglong2 wa = wp[0];   // packed weights for co, co+1
                ulonglong2 wc = wp[1];   // packed weights for co+2, co+3
                #pragma unroll
                for (int j = 0; j < 4; j++) {
                    ull ip = p[kx + 2 * j];
                    fma2(acc[0 + j],  ip, wa.x);
                    fma2(acc[4 + j],  ip, wa.y);
                    fma2(acc[8 + j],  ip, wc.x);
                    fma2(acc[12 + j], ip, wc.y);
                }
            }
        }
    }

    // ---- store (+bias), guarding right/bottom edges
    const int oy = oh0 + py;
    if (oy < OHh) {
        #pragma unroll
        for (int c = 0; c < 4; ++c) {
            int co = cog * 4 + c;
            float bs = bias[co];
            float* op = out + (((size_t)b * CO_ + co) * OHh + oy) * OWw + ow0 + px;
            #pragma unroll
            for (int j = 0; j < 4; j++) {
                float lo, hi;
                unpk2(acc[c * 4 + j], lo, hi);
                int ox = ow0 + px + 2 * j;
                if (ox < OWw)     op[2 * j]     = lo + bs;
                if (ox + 1 < OWw) op[2 * j + 1] = hi + bs;
            }
        }
    }
}

extern "C" void kernel_launch(void* const* d_in, const int* in_sizes, int n_in,
                              void* d_out, int out_size)
{
    const float* x    = (const float*)d_in[0];
    const float* w    = (const float*)d_in[1];
    const float* bias = (const float*)d_in[2];
    float* out        = (float*)d_out;

    cudaFuncSetAttribute(conv3x3_f32x2,
                         cudaFuncAttributeMaxDynamicSharedMemorySize, SMEM_BYTES);
    conv3x3_f32x2<<<B_ * YT * XT, THREADS, SMEM_BYTES>>>(x, w, bias, out);
}

// round 2
// speedup vs baseline: 1.3941x; 1.3941x over previous
#include <cuda_runtime.h>
#include <cstdint>
#include <cstddef>

// Problem constants
#define B_   16
#define CI_  32
#define HH   224
#define WW   224
#define CO_  32
#define OH_  222
#define OW_  222

// Tiling: CTA = 256 threads = 8 warps. Each warp = 32 lanes = 32 output channels,
// all lanes share one 8-wide x 2-high pixel patch. CTA tile = 16 wide x 8 high.
#define TW   16
#define TH   8
#define XT   14          // ceil(222/16)
#define YT   28          // ceil(222/8)
#define THREADS 256

#define IN_ROWS   10     // TH + 2 halo
#define IN_STRIDE 20     // TW + 2 halo, padded to float4 multiple
#define SIN_FLOATS (CI_ * IN_ROWS * IN_STRIDE)   // 6400
#define SW_FLOATS  (CI_ * 9 * CO_)               // 9216, layout [ci*9+tap][co]
#define SMEM_BYTES ((SIN_FLOATS + SW_FLOATS) * 4) // 62464 B -> 3 CTAs/SM

typedef unsigned long long ull;

// Packed fp32x2 (sm_103a packed-f32 pipe: 2 MACs per FFMA2)
__device__ __forceinline__ ull pk2(float a, float b) {
    ull r;
    asm("mov.b64 %0, {%1, %2};" : "=l"(r) : "f"(a), "f"(b));
    return r;
}
__device__ __forceinline__ void fma2(ull& d, ull a, ull b) {
    asm("fma.rn.f32x2 %0, %1, %2, %0;" : "+l"(d) : "l"(a), "l"(b));
}
__device__ __forceinline__ void unpk2(ull v, float& lo, float& hi) {
    asm("mov.b64 {%0, %1}, %2;" : "=f"(lo), "=f"(hi) : "l"(v));
}

__global__ void __launch_bounds__(THREADS, 3)
conv3x3_lane_co(const float* __restrict__ x,
                const float* __restrict__ w,
                const float* __restrict__ bias,
                float* __restrict__ out)
{
    extern __shared__ float smem[];
    float* sIn = smem;                 // [ci][10][20], row base 16B-aligned
    float* sW  = smem + SIN_FLOATS;    // [ci*9+tap][co] -- lane-consecutive

    const int tid = threadIdx.x;
    const int bid = blockIdx.x;
    const int bx  = bid % XT;
    const int by  = (bid / XT) % YT;
    const int b   = bid / (XT * YT);
    const int ow0 = bx * TW;
    const int oh0 = by * TH;

    // ---- weights -> smem [r=ci*9+tap][co]; conflict-free smem stores
    // (strided gmem reads; weights are 36KB total, L2-hot after first wave)
    {
        const int co = tid & 31;
        for (int r = tid >> 5; r < CI_ * 9; r += THREADS >> 5) {
            sW[r * 32 + co] = __ldg(&w[co * (CI_ * 9) + r]);
        }
    }

    // ---- input tile -> smem (zero-fill out of range)
    const float* xb = x + (size_t)b * CI_ * HH * WW;
    for (int i = tid; i < SIN_FLOATS; i += THREADS) {
        int c  = i % IN_STRIDE;
        int t  = i / IN_STRIDE;
        int r  = t % IN_ROWS;
        int ci = t / IN_ROWS;
        int ih = oh0 + r;
        int iw = ow0 + c;
        float v = 0.f;
        if (ih < HH && iw < WW) v = __ldg(&xb[(size_t)ci * HH * WW + ih * WW + iw]);
        sIn[i] = v;
    }
    __syncthreads();

    // ---- warp geometry: lane = co; warp picks an 8x2 pixel patch
    const int lane = tid & 31;
    const int wid  = tid >> 5;
    const int px0  = (wid & 1) * 8;        // 0 or 8 within tile
    const int ry0  = (wid >> 1) * 2;       // output rows ry0, ry0+1 within tile

    ull acc[8];                            // [out_row 0..1][pair 0..3]
    #pragma unroll
    for (int i = 0; i < 8; i++) acc[i] = 0ULL;

    const float* inb = sIn + ry0 * IN_STRIDE + px0;  // broadcast reads
    const float* wl  = sW + lane;

    #pragma unroll 1
    for (int ci = 0; ci < CI_; ++ci) {
        // 9 per-lane weights for this ci, duplicated into f32x2 lanes
        ull wr[9];
        #pragma unroll
        for (int t = 0; t < 9; ++t) {
            float wv = wl[(ci * 9 + t) * 32];   // LDS.32, lanes consecutive
            wr[t] = pk2(wv, wv);
        }

        const float* rb = inb + ci * (IN_ROWS * IN_STRIDE);
        #pragma unroll
        for (int r = 0; r < 4; ++r) {          // 4 input rows feed 2 output rows
            const float4* rp = (const float4*)(rb + r * IN_STRIDE);
            float4 A = rp[0], Bv = rp[1], Cv = rp[2];  // warp-broadcast LDS.128
            float f[10] = {A.x, A.y, A.z, A.w, Bv.x, Bv.y, Bv.z, Bv.w, Cv.x, Cv.y};
            ull p[9];
            #pragma unroll
            for (int s = 0; s < 9; s++) p[s] = pk2(f[s], f[s + 1]);

            if (r <= 2) {   // out row 0, ky = r
                #pragma unroll
                for (int kx = 0; kx < 3; kx++)
                    #pragma unroll
                    for (int j = 0; j < 4; j++)
                        fma2(acc[j], p[kx + 2 * j], wr[r * 3 + kx]);
            }
            if (r >= 1) {   // out row 1, ky = r - 1
                #pragma unroll
                for (int kx = 0; kx < 3; kx++)
                    #pragma unroll
                    for (int j = 0; j < 4; j++)
                        fma2(acc[4 + j], p[kx + 2 * j], wr[(r - 1) * 3 + kx]);
            }
        }
    }

    // ---- epilogue: +bias, store (float2 when fully in range)
    const float bs  = bias[lane];
    const int   ox0 = ow0 + px0;
    #pragma unroll
    for (int r = 0; r < 2; r++) {
        int oy = oh0 + ry0 + r;
        if (oy >= OH_) continue;
        float* op = out + ((size_t)(b * CO_ + lane) * OH_ + oy) * OW_ + ox0;
        float v[8];
        #pragma unroll
        for (int j = 0; j < 4; j++) unpk2(acc[r * 4 + j], v[2 * j], v[2 * j + 1]);
        #pragma unroll
        for (int j = 0; j < 8; j++) v[j] += bs;

        if (ox0 + 8 <= OW_) {
            #pragma unroll
            for (int j = 0; j < 4; j++)
                ((float2*)op)[j] = make_float2(v[2 * j], v[2 * j + 1]);  // 8B-aligned
        } else {
            #pragma unroll
            for (int j = 0; j < 8; j++)
                if (ox0 + j < OW_) op[j] = v[j];
        }
    }
}

extern "C" void kernel_launch(void* const* d_in, const int* in_sizes, int n_in,
                              void* d_out, int out_size)
{
    const float* x    = (const float*)d_in[0];
    const float* w    = (const float*)d_in[1];
    const float* bias = (const float*)d_in[2];
    float* out        = (float*)d_out;

    cudaFuncSetAttribute(conv3x3_lane_co,
                         cudaFuncAttributeMaxDynamicSharedMemorySize, SMEM_BYTES);
    conv3x3_lane_co<<<B_ * YT * XT, THREADS, SMEM_BYTES>>>(x, w, bias, out);
}

// round 3
// speedup vs baseline: 1.4757x; 1.0585x over previous
#include <cuda_runtime.h>
#include <cstdint>
#include <cstddef>

// Problem constants
#define B_   16
#define CI_  32
#define HH   224
#define WW   224
#define CO_  32
#define OH_  222
#define OW_  222

// Tiling: CTA = 256 threads = 8 warps. lane = co. Each warp: 8 px wide x 4 rows.
// Warps arranged 2 wide x 4 high -> CTA tile 16 x 16.
#define TW   16
#define TH   16
#define XT   14          // ceil(222/16)
#define YT   14          // ceil(222/16)
#define THREADS 256

#define IN_ROWS   18     // TH + 2 halo
#define IN_STRIDE 20     // TW + 2 halo, padded for float4
#define SIN_FLOATS (CI_ * IN_ROWS * IN_STRIDE)   // 11520
#define SW_FLOATS  (CI_ * 9 * CO_)               // 9216  [ci*9+tap][co]
#define SMEM_BYTES ((SIN_FLOATS + SW_FLOATS) * 4) // 82944 -> 2 CTAs/SM

typedef unsigned long long ull;

__device__ __forceinline__ ull pk2(float a, float b) {
    ull r;
    asm("mov.b64 %0, {%1, %2};" : "=l"(r) : "f"(a), "f"(b));
    return r;
}
__device__ __forceinline__ void fma2(ull& d, ull a, ull b) {
    asm("fma.rn.f32x2 %0, %1, %2, %0;" : "+l"(d) : "l"(a), "l"(b));
}
__device__ __forceinline__ void unpk2(ull v, float& lo, float& hi) {
    asm("mov.b64 {%0, %1}, %2;" : "=f"(lo), "=f"(hi) : "l"(v));
}

__global__ void __launch_bounds__(THREADS, 2)
conv3x3_r4(const float* __restrict__ x,
           const float* __restrict__ w,
           const float* __restrict__ bias,
           float* __restrict__ out)
{
    extern __shared__ float smem[];
    float* sIn = smem;                 // [ci][18][20]
    float* sW  = smem + SIN_FLOATS;    // [ci*9+tap][co]

    const int tid = threadIdx.x;
    const int bid = blockIdx.x;
    const int bx  = bid % XT;
    const int by  = (bid / XT) % YT;
    const int b   = bid / (XT * YT);
    const int ow0 = bx * TW;
    const int oh0 = by * TH;

    // ---- weights -> smem [ci*9+tap][co]
    {
        const int co = tid & 31;
        for (int r = tid >> 5; r < CI_ * 9; r += THREADS >> 5) {
            sW[r * 32 + co] = __ldg(&w[co * (CI_ * 9) + r]);
        }
    }

    // ---- input tile -> smem (zero-fill OOB)
    const float* xb = x + (size_t)b * CI_ * HH * WW;
    for (int i = tid; i < SIN_FLOATS; i += THREADS) {
        int c  = i % IN_STRIDE;
        int t  = i / IN_STRIDE;
        int r  = t % IN_ROWS;
        int ci = t / IN_ROWS;
        int ih = oh0 + r;
        int iw = ow0 + c;
        float v = 0.f;
        if (ih < HH && iw < WW) v = __ldg(&xb[(size_t)ci * HH * WW + ih * WW + iw]);
        sIn[i] = v;
    }
    __syncthreads();

    // ---- warp geometry: lane = co; warp patch = 8 px x 4 output rows
    const int lane = tid & 31;
    const int wid  = tid >> 5;
    const int px0  = (wid & 1) * 8;     // 0 or 8
    const int ry0  = (wid >> 1) * 4;    // 0,4,8,12

    ull acc[16];                        // [out_row 0..3][pair 0..3]
    #pragma unroll
    for (int i = 0; i < 16; i++) acc[i] = 0ULL;

    const float* inb = sIn + ry0 * IN_STRIDE + px0;
    const float* wl  = sW + lane;

    #pragma unroll 1
    for (int ci = 0; ci < CI_; ++ci) {
        ull wr[9];
        #pragma unroll
        for (int t = 0; t < 9; ++t) {
            float wv = wl[(ci * 9 + t) * 32];   // LDS.32 lane-consecutive
            wr[t] = pk2(wv, wv);
        }

        const float* rb = inb + ci * (IN_ROWS * IN_STRIDE);
        #pragma unroll
        for (int r = 0; r < 6; ++r) {           // 6 input rows -> 4 output rows
            const float4* rp = (const float4*)(rb + r * IN_STRIDE);
            float4 A = rp[0], Bv = rp[1], Cv = rp[2];   // broadcast LDS.128
            float f[10] = {A.x, A.y, A.z, A.w, Bv.x, Bv.y, Bv.z, Bv.w, Cv.x, Cv.y};
            ull p[9];
            #pragma unroll
            for (int s = 0; s < 9; s++) p[s] = pk2(f[s], f[s + 1]);

            // input row r feeds output rows o = r-2 .. r (clipped to 0..3), ky = r - o
            #pragma unroll
            for (int o = 0; o < 4; ++o) {
                if (o > r || o < r - 2) continue;   // compile-time resolved
                const int ky = r - o;
                #pragma unroll
                for (int kx = 0; kx < 3; kx++)
                    #pragma unroll
                    for (int j = 0; j < 4; j++)
                        fma2(acc[o * 4 + j], p[kx + 2 * j], wr[ky * 3 + kx]);
            }
        }
    }

    // ---- epilogue: +bias, store
    const float bs  = bias[lane];
    const int   ox0 = ow0 + px0;
    #pragma unroll
    for (int o = 0; o < 4; o++) {
        int oy = oh0 + ry0 + o;
        if (oy >= OH_) continue;
        float* op = out + ((size_t)(b * CO_ + lane) * OH_ + oy) * OW_ + ox0;
        float v[8];
        #pragma unroll
        for (int j = 0; j < 4; j++) unpk2(acc[o * 4 + j], v[2 * j], v[2 * j + 1]);
        #pragma unroll
        for (int j = 0; j < 8; j++) v[j] += bs;

        if (ox0 + 8 <= OW_) {
            #pragma unroll
            for (int j = 0; j < 4; j++)
                ((float2*)op)[j] = make_float2(v[2 * j], v[2 * j + 1]);
        } else {
            #pragma unroll
            for (int j = 0; j < 8; j++)
                if (ox0 + j < OW_) op[j] = v[j];
        }
    }
}

extern "C" void kernel_launch(void* const* d_in, const int* in_sizes, int n_in,
                              void* d_out, int out_size)
{
    const float* x    = (const float*)d_in[0];
    const float* w    = (const float*)d_in[1];
    const float* bias = (const float*)d_in[2];
    float* out        = (float*)d_out;

    cudaFuncSetAttribute(conv3x3_r4,
                         cudaFuncAttributeMaxDynamicSharedMemorySize, SMEM_BYTES);
    conv3x3_r4<<<B_ * YT * XT, THREADS, SMEM_BYTES>>>(x, w, bias, out);
}

// round 4
// speedup vs baseline: 1.6711x; 1.1324x over previous
#include <cuda_runtime.h>
#include <cstdint>
#include <cstddef>

// Problem constants
#define B_   16
#define CI_  32
#define HH   224
#define WW   224
#define CO_  32
#define OH_  222
#define OW_  222

// CTA = 256 threads = 8 warps. Warp covers 16 px wide x 2 output rows x all 32 co.
// lane&15 = co-pair (co = 2cp, 2cp+1), lane>>4 = pixel half (8 px each).
// Warps stack vertically: CTA tile = 16 wide x 16 high.
#define TW   16
#define TH   16
#define XT   14          // ceil(222/16)
#define YT   14
#define THREADS 256

#define IN_ROWS   18     // TH + 2
#define IN_STRIDE 20     // TW + 2 halo, padded for float4
#define SIN_FLOATS (CI_ * IN_ROWS * IN_STRIDE)    // 11520
#define SW_FLOATS  (CI_ * 9 * CO_)                // 9216  [ci*9+tap][co]
#define SMEM_BYTES ((SIN_FLOATS + SW_FLOATS) * 4) // 82944 -> 2 CTAs/SM

typedef unsigned long long ull;

__device__ __forceinline__ ull pk2(float a, float b) {
    ull r;
    asm("mov.b64 %0, {%1, %2};" : "=l"(r) : "f"(a), "f"(b));
    return r;
}
__device__ __forceinline__ void fma2(ull& d, ull a, ull b) {
    asm("fma.rn.f32x2 %0, %1, %2, %0;" : "+l"(d) : "l"(a), "l"(b));
}
__device__ __forceinline__ void unpk2(ull v, float& lo, float& hi) {
    asm("mov.b64 {%0, %1}, %2;" : "=f"(lo), "=f"(hi) : "l"(v));
}

__global__ void __launch_bounds__(THREADS, 2)
conv3x3_copack(const float* __restrict__ x,
               const float* __restrict__ w,
               const float* __restrict__ bias,
               float* __restrict__ out)
{
    extern __shared__ float smem[];
    float* sIn = smem;                 // [ci][18][20]
    float* sW  = smem + SIN_FLOATS;    // [ci*9+tap][co] -- co-pair readable as ull

    const int tid = threadIdx.x;
    const int bid = blockIdx.x;
    const int bx  = bid % XT;
    const int by  = (bid / XT) % YT;
    const int b   = bid / (XT * YT);
    const int ow0 = bx * TW;
    const int oh0 = by * TH;

    // ---- weights -> smem [ci*9+tap][co]
    {
        const int co = tid & 31;
        for (int r = tid >> 5; r < CI_ * 9; r += THREADS >> 5) {
            sW[r * 32 + co] = __ldg(&w[co * (CI_ * 9) + r]);
        }
    }

    // ---- input tile -> smem (zero-fill OOB)
    const float* xb = x + (size_t)b * CI_ * HH * WW;
    for (int i = tid; i < SIN_FLOATS; i += THREADS) {
        int c  = i % IN_STRIDE;
        int t  = i / IN_STRIDE;
        int r  = t % IN_ROWS;
        int ci = t / IN_ROWS;
        int ih = oh0 + r;
        int iw = ow0 + c;
        float v = 0.f;
        if (ih < HH && iw < WW) v = __ldg(&xb[(size_t)ci * HH * WW + ih * WW + iw]);
        sIn[i] = v;
    }
    __syncthreads();

    const int lane = tid & 31;
    const int wid  = tid >> 5;
    const int cp   = lane & 15;        // co pair index: co = 2cp, 2cp+1
    const int ph   = lane >> 4;        // pixel half
    const int px0  = ph * 8;
    const int ry0  = wid * 2;

    ull acc[16];                       // [row 0..1][px 0..7], each = (co0, co1)
    #pragma unroll
    for (int i = 0; i < 16; i++) acc[i] = 0ULL;

    const ull*   wpair = (const ull*)sW;               // [(ci*9+t)*16 + cp]
    const float* inb   = sIn + ry0 * IN_STRIDE + px0;

    #pragma unroll 1
    for (int ci = 0; ci < CI_; ++ci) {
        // 9 weight pairs: direct LDS.64, NO movs
        ull wr[9];
        #pragma unroll
        for (int t = 0; t < 9; ++t)
            wr[t] = wpair[(ci * 9 + t) * 16 + cp];

        const float* rb = inb + ci * (IN_ROWS * IN_STRIDE);
        #pragma unroll
        for (int r = 0; r < 4; ++r) {          // 4 input rows -> 2 output rows
            const float4* rp = (const float4*)(rb + r * IN_STRIDE);
            float4 A = rp[0], Bv = rp[1], Cv = rp[2];   // broadcast per half-warp
            float f[10] = {A.x, A.y, A.z, A.w, Bv.x, Bv.y, Bv.z, Bv.w, Cv.x, Cv.y};
            ull d[10];
            #pragma unroll
            for (int s = 0; s < 10; s++) d[s] = pk2(f[s], f[s]);  // 1 mov each

            if (r <= 2) {                       // out row 0, ky = r
                #pragma unroll
                for (int kx = 0; kx < 3; kx++)
                    #pragma unroll
                    for (int p = 0; p < 8; p++)
                        fma2(acc[p], d[p + kx], wr[r * 3 + kx]);
            }
            if (r >= 1) {                       // out row 1, ky = r - 1
                #pragma unroll
                for (int kx = 0; kx < 3; kx++)
                    #pragma unroll
                    for (int p = 0; p < 8; p++)
                        fma2(acc[8 + p], d[p + kx], wr[(r - 1) * 3 + kx]);
            }
        }
    }

    // ---- epilogue: +bias, store per co row (float2, 8B-aligned: 222 even)
    const int co0 = 2 * cp;
    const float b0 = bias[co0];
    const float b1 = bias[co0 + 1];
    const int  ox0 = ow0 + px0;

    #pragma unroll
    for (int r = 0; r < 2; r++) {
        int oy = oh0 + ry0 + r;
        if (oy >= OH_) continue;
        float v0[8], v1[8];
        #pragma unroll
        for (int p = 0; p < 8; p++) {
            unpk2(acc[r * 8 + p], v0[p], v1[p]);
            v0[p] += b0; v1[p] += b1;
        }
        float* o0 = out + ((size_t)(b * CO_ + co0)     * OH_ + oy) * OW_ + ox0;
        float* o1 = out + ((size_t)(b * CO_ + co0 + 1) * OH_ + oy) * OW_ + ox0;
        if (ox0 + 8 <= OW_) {
            #pragma unroll
            for (int j = 0; j < 4; j++) {
                ((float2*)o0)[j] = make_float2(v0[2 * j], v0[2 * j + 1]);
                ((float2*)o1)[j] = make_float2(v1[2 * j], v1[2 * j + 1]);
            }
        } else {
            #pragma unroll
            for (int j = 0; j < 8; j++) {
                if (ox0 + j < OW_) { o0[j] = v0[j]; o1[j] = v1[j]; }
            }
        }
    }
}

extern "C" void kernel_launch(void* const* d_in, const int* in_sizes, int n_in,
                              void* d_out, int out_size)
{
    const float* x    = (const float*)d_in[0];
    const float* w    = (const float*)d_in[1];
    const float* bias = (const float*)d_in[2];
    float* out        = (float*)d_out;

    cudaFuncSetAttribute(conv3x3_copack,
                         cudaFuncAttributeMaxDynamicSharedMemorySize, SMEM_BYTES);
    conv3x3_copack<<<B_ * YT * XT, THREADS, SMEM_BYTES>>>(x, w, bias, out);
}

// round 5
// speedup vs baseline: 1.6866x; 1.0093x over previous
#include <cuda_runtime.h>
#include <cstdint>
#include <cstddef>

// Problem constants
#define B_   16
#define CI_  32
#define HH   224
#define WW   224
#define CO_  32
#define OH_  222
#define OW_  222

// CTA = 384 threads = 12 warps. Warp covers 16 px wide x 2 output rows x all 32 co.
// lane&15 = co-pair (co = 2cp, 2cp+1), lane>>4 = pixel half (8 px each).
// Warps stack vertically: CTA tile = 16 wide x 24 high.
#define TW   16
#define TH   24
#define XT   14          // ceil(222/16)
#define YT   10          // ceil(222/24)
#define THREADS 384

#define IN_ROWS   26     // TH + 2
#define IN_STRIDE 20     // TW + 2 halo, padded for float4
#define SIN_FLOATS (CI_ * IN_ROWS * IN_STRIDE)    // 16640
#define SW_FLOATS  (CI_ * 9 * CO_)                // 9216  [ci*9+tap][co]
#define SMEM_BYTES ((SIN_FLOATS + SW_FLOATS) * 4) // 103424 -> 2 CTAs/SM, 24 warps

typedef unsigned long long ull;

__device__ __forceinline__ ull pk2(float a, float b) {
    ull r;
    asm("mov.b64 %0, {%1, %2};" : "=l"(r) : "f"(a), "f"(b));
    return r;
}
__device__ __forceinline__ void fma2(ull& d, ull a, ull b) {
    asm("fma.rn.f32x2 %0, %1, %2, %0;" : "+l"(d) : "l"(a), "l"(b));
}
__device__ __forceinline__ void unpk2(ull v, float& lo, float& hi) {
    asm("mov.b64 {%0, %1}, %2;" : "=f"(lo), "=f"(hi) : "l"(v));
}

__global__ void __launch_bounds__(THREADS, 2)
conv3x3_copack24(const float* __restrict__ x,
                 const float* __restrict__ w,
                 const float* __restrict__ bias,
                 float* __restrict__ out)
{
    extern __shared__ float smem[];
    float* sIn = smem;                 // [ci][26][20]
    float* sW  = smem + SIN_FLOATS;    // [ci*9+tap][co] -- co-pair readable as ull

    const int tid = threadIdx.x;
    const int bid = blockIdx.x;
    const int bx  = bid % XT;
    const int by  = (bid / XT) % YT;
    const int b   = bid / (XT * YT);
    const int ow0 = bx * TW;
    const int oh0 = by * TH;

    // ---- weights -> smem [ci*9+tap][co]
    {
        const int co = tid & 31;
        for (int r = tid >> 5; r < CI_ * 9; r += THREADS >> 5) {
            sW[r * 32 + co] = __ldg(&w[co * (CI_ * 9) + r]);
        }
    }

    // ---- input tile -> smem (zero-fill OOB)
    const float* xb = x + (size_t)b * CI_ * HH * WW;
    for (int i = tid; i < SIN_FLOATS; i += THREADS) {
        int c  = i % IN_STRIDE;
        int t  = i / IN_STRIDE;
        int r  = t % IN_ROWS;
        int ci = t / IN_ROWS;
        int ih = oh0 + r;
        int iw = ow0 + c;
        float v = 0.f;
        if (ih < HH && iw < WW) v = __ldg(&xb[(size_t)ci * HH * WW + ih * WW + iw]);
        sIn[i] = v;
    }
    __syncthreads();

    const int lane = tid & 31;
    const int wid  = tid >> 5;         // 0..11
    const int cp   = lane & 15;        // co pair index: co = 2cp, 2cp+1
    const int ph   = lane >> 4;        // pixel half
    const int px0  = ph * 8;
    const int ry0  = wid * 2;          // output rows ry0, ry0+1 within tile

    ull acc[16];                       // [row 0..1][px 0..7], each = (co0, co1)
    #pragma unroll
    for (int i = 0; i < 16; i++) acc[i] = 0ULL;

    const ull*   wpair = (const ull*)sW;               // [(ci*9+t)*16 + cp]
    const float* inb   = sIn + ry0 * IN_STRIDE + px0;

    #pragma unroll 1
    for (int ci = 0; ci < CI_; ++ci) {
        // 9 weight pairs: direct LDS.64, no movs
        ull wr[9];
        #pragma unroll
        for (int t = 0; t < 9; ++t)
            wr[t] = wpair[(ci * 9 + t) * 16 + cp];

        const float* rb = inb + ci * (IN_ROWS * IN_STRIDE);
        #pragma unroll
        for (int r = 0; r < 4; ++r) {          // 4 input rows -> 2 output rows
            const float4* rp = (const float4*)(rb + r * IN_STRIDE);
            float4 A = rp[0], Bv = rp[1], Cv = rp[2];   // broadcast per half-warp
            float f[10] = {A.x, A.y, A.z, A.w, Bv.x, Bv.y, Bv.z, Bv.w, Cv.x, Cv.y};
            ull d[10];
            #pragma unroll
            for (int s = 0; s < 10; s++) d[s] = pk2(f[s], f[s]);  // 1 mov each

            if (r <= 2) {                       // out row 0, ky = r
                #pragma unroll
                for (int kx = 0; kx < 3; kx++)
                    #pragma unroll
                    for (int p = 0; p < 8; p++)
                        fma2(acc[p], d[p + kx], wr[r * 3 + kx]);
            }
            if (r >= 1) {                       // out row 1, ky = r - 1
                #pragma unroll
                for (int kx = 0; kx < 3; kx++)
                    #pragma unroll
                    for (int p = 0; p < 8; p++)
                        fma2(acc[8 + p], d[p + kx], wr[(r - 1) * 3 + kx]);
            }
        }
    }

    // ---- epilogue: +bias, store per co row (float2; OW_=222 is even -> aligned)
    const int co0 = 2 * cp;
    const float b0 = bias[co0];
    const float b1 = bias[co0 + 1];
    const int  ox0 = ow0 + px0;

    #pragma unroll
    for (int r = 0; r < 2; r++) {
        int oy = oh0 + ry0 + r;
        if (oy >= OH_) continue;
        float v0[8], v1[8];
        #pragma unroll
        for (int p = 0; p < 8; p++) {
            unpk2(acc[r * 8 + p], v0[p], v1[p]);
            v0[p] += b0; v1[p] += b1;
        }
        float* o0 = out + ((size_t)(b * CO_ + co0)     * OH_ + oy) * OW_ + ox0;
        float* o1 = out + ((size_t)(b * CO_ + co0 + 1) * OH_ + oy) * OW_ + ox0;
        if (ox0 + 8 <= OW_) {
            #pragma unroll
            for (int j = 0; j < 4; j++) {
                ((float2*)o0)[j] = make_float2(v0[2 * j], v0[2 * j + 1]);
                ((float2*)o1)[j] = make_float2(v1[2 * j], v1[2 * j + 1]);
            }
        } else {
            #pragma unroll
            for (int j = 0; j < 8; j++) {
                if (ox0 + j < OW_) { o0[j] = v0[j]; o1[j] = v1[j]; }
            }
        }
    }
}

extern "C" void kernel_launch(void* const* d_in, const int* in_sizes, int n_in,
                              void* d_out, int out_size)
{
    const float* x    = (const float*)d_in[0];
    const float* w    = (const float*)d_in[1];
    const float* bias = (const float*)d_in[2];
    float* out        = (float*)d_out;

    cudaFuncSetAttribute(conv3x3_copack24,
                         cudaFuncAttributeMaxDynamicSharedMemorySize, SMEM_BYTES);
    conv3x3_copack24<<<B_ * YT * XT, THREADS, SMEM_BYTES>>>(x, w, bias, out);
}

// round 7
// speedup vs baseline: 2.7152x; 1.6099x over previous
#include <cuda_runtime.h>
#include <cstdint>
#include <cstddef>

#define B_   16
#define CI_  32
#define HH   224
#define WW   224
#define CO_  32
#define OH_  222
#define OW_  222

// ---------------- converted-operand global buffers (module-load static) ----
// x converted: per (b,h,w): 32 words = [16 hi bf16x2 words][16 lo words] (128B)
static __device__ __align__(16) unsigned int g_xcvt[(size_t)B_ * HH * WW * 32];
// w converted: per (tap,co): 32 words = [16 hi][16 lo]
static __device__ __align__(16) unsigned int g_wcvt[9 * CO_ * 32];

// ---------------- main-kernel tiling ----------------
// CTA: 512 thr = 16 warps. Tile: 4 output rows x 128 px x 32 co.
// warp: orow = wid&3, mquad = wid>>2 -> 32 px (2 m16 tiles) x 32 co (4 n8 tiles)
#define THREADS 512
#define XT 2            // px0 = 0 or 94  (94+128 = 222)
#define YT 56           // ceil(222/4)
#define TROWS 6         // 4 output rows + 2 halo
#define TCOLS 136       // 128 px + 2 halo, padded to 136
// smem cell = one (row,col): 36 words: hi pairs at w0..15, pad 16..19, lo at 20..35
#define CELLW 36
#define SA_WORDS (TROWS * TCOLS * CELLW)      // 29376
#define SB_WORDS (9 * CO_ * CELLW)            // 10368
#define SMEM_WORDS (SA_WORDS + SB_WORDS)      // 39744
#define SMEM_BYTES (SMEM_WORDS * 4)           // 158976

__device__ __forceinline__ unsigned pack_hi_trunc(unsigned u0, unsigned u1) {
    unsigned d;  // {lo16: u0>>16, hi16: u1>>16}
    asm("prmt.b32 %0, %1, %2, 0x7632;" : "=r"(d) : "r"(u0), "r"(u1));
    return d;
}
__device__ __forceinline__ unsigned pack_bf16x2(float even, float odd) {
    unsigned d;  // lower = bf16(even), upper = bf16(odd)
    asm("cvt.rn.bf16x2.f32 %0, %1, %2;" : "=r"(d) : "f"(odd), "f"(even));
    return d;
}
__device__ __forceinline__ void mma_bf16(float* c, unsigned a0, unsigned a1,
                                         unsigned a2, unsigned a3,
                                         unsigned b0, unsigned b1) {
    asm volatile(
        "mma.sync.aligned.m16n8k16.row.col.f32.bf16.bf16.f32 "
        "{%0,%1,%2,%3}, {%4,%5,%6,%7}, {%8,%9}, {%0,%1,%2,%3};"
        : "+f"(c[0]), "+f"(c[1]), "+f"(c[2]), "+f"(c[3])
        : "r"(a0), "r"(a1), "r"(a2), "r"(a3), "r"(b0), "r"(b1));
}

// ---------------- pre-pass: convert x to bf16 hi/lo, layout [b][h][w][32w] ----
__global__ void __launch_bounds__(256) cvt_x(const float* __restrict__ x) {
    const int lane = threadIdx.x & 31;
    const int W    = (blockIdx.x * 256 + threadIdx.x) >> 5;   // warp task id
    const int wb   = W % 7;
    const int h    = (W / 7) % HH;
    const int b    = W / (7 * HH);
    if (b >= B_) return;
    const int w = wb * 32 + lane;

    unsigned hw[16], lw[16];
    #pragma unroll
    for (int p = 0; p < 16; ++p) {
        size_t i0 = (((size_t)b * CI_ + 2 * p) * HH + h) * WW + w;
        float v0 = __ldg(&x[i0]);
        float v1 = __ldg(&x[i0 + (size_t)HH * WW]);
        unsigned u0 = __float_as_uint(v0), u1 = __float_as_uint(v1);
        hw[p] = pack_hi_trunc(u0, u1);
        float l0 = v0 - __uint_as_float(u0 & 0xffff0000u);
        float l1 = v1 - __uint_as_float(u1 & 0xffff0000u);
        lw[p] = pack_bf16x2(l0, l1);
    }
    unsigned* dst = g_xcvt + (((size_t)b * HH + h) * WW + w) * 32;
    uint4* d4 = (uint4*)dst;
    #pragma unroll
    for (int j = 0; j < 4; ++j)
        d4[j] = make_uint4(hw[4 * j], hw[4 * j + 1], hw[4 * j + 2], hw[4 * j + 3]);
    #pragma unroll
    for (int j = 0; j < 4; ++j)
        d4[4 + j] = make_uint4(lw[4 * j], lw[4 * j + 1], lw[4 * j + 2], lw[4 * j + 3]);
}

// ---------------- pre-pass: convert w, layout [tap*32+co][32w] ----
__global__ void __launch_bounds__(288) cvt_w(const float* __restrict__ w) {
    const int r = threadIdx.x;       // r = tap*32 + co
    if (r >= 288) return;
    const int tap = r >> 5, co = r & 31;
    unsigned hw[16], lw[16];
    #pragma unroll
    for (int p = 0; p < 16; ++p) {
        float v0 = __ldg(&w[co * 288 + (2 * p) * 9 + tap]);
        float v1 = __ldg(&w[co * 288 + (2 * p + 1) * 9 + tap]);
        unsigned u0 = __float_as_uint(v0), u1 = __float_as_uint(v1);
        hw[p] = pack_hi_trunc(u0, u1);
        lw[p] = pack_bf16x2(v0 - __uint_as_float(u0 & 0xffff0000u),
                            v1 - __uint_as_float(u1 & 0xffff0000u));
    }
    uint4* d4 = (uint4*)(g_wcvt + (size_t)r * 32);
    #pragma unroll
    for (int j = 0; j < 4; ++j)
        d4[j] = make_uint4(hw[4 * j], hw[4 * j + 1], hw[4 * j + 2], hw[4 * j + 3]);
    #pragma unroll
    for (int j = 0; j < 4; ++j)
        d4[4 + j] = make_uint4(lw[4 * j], lw[4 * j + 1], lw[4 * j + 2], lw[4 * j + 3]);
}

// ---------------- main: implicit-GEMM conv via mma.sync bf16 split ----------
__global__ void __launch_bounds__(THREADS, 1)
conv3x3_mma(const float* __restrict__ bias, float* __restrict__ out) {
    extern __shared__ unsigned smw[];
    unsigned* sA = smw;               // [trow][col][36w]
    unsigned* sB = smw + SA_WORDS;    // [tap*32+co][36w]

    const int tid = threadIdx.x;
    const int blk = blockIdx.x;
    const int bx  = blk & 1;
    const int by  = (blk >> 1) % YT;
    const int b   = blk / (2 * YT);
    const int px0 = bx ? 94 : 0;
    const int oh0 = by * 4;

    // ---- copy B: 288 rows x 8 16B-chunks (128B src -> 144B padded dst)
    for (int c = tid; c < 288 * 8; c += THREADS) {
        int row = c >> 3, sub = c & 7;
        uint4 v = *(const uint4*)(g_wcvt + (size_t)row * 32 + sub * 4);
        int dw = row * CELLW + (sub < 4 ? sub * 4 : 20 + (sub - 4) * 4);
        *(uint4*)(sB + dw) = v;
    }
    // ---- copy A tile: 816 cells x 8 chunks, zero-fill OOB
    for (int c = tid; c < TROWS * TCOLS * 8; c += THREADS) {
        int cell = c >> 3, sub = c & 7;
        int trow = cell / TCOLS, col = cell % TCOLS;
        int ih = oh0 + trow, iw = px0 + col;
        uint4 v = make_uint4(0, 0, 0, 0);
        if (ih < HH && iw < WW)
            v = *(const uint4*)(g_xcvt + (((size_t)b * HH + ih) * WW + iw) * 32 + sub * 4);
        int dw = cell * CELLW + (sub < 4 ? sub * 4 : 20 + (sub - 4) * 4);
        *(uint4*)(sA + dw) = v;
    }
    __syncthreads();

    const int lane = tid & 31;
    const int wid  = tid >> 5;
    const int g = lane >> 2, t = lane & 3;
    const int orow = wid & 3;
    const int mq   = wid >> 2;              // pixel quad: 32 px each

    float acc[2][4][4];
    #pragma unroll
    for (int mt = 0; mt < 2; mt++)
        #pragma unroll
        for (int nt = 0; nt < 4; nt++)
            #pragma unroll
            for (int i = 0; i < 4; i++) acc[mt][nt][i] = 0.f;

    #pragma unroll 1
    for (int ky = 0; ky < 3; ++ky) {
        #pragma unroll
        for (int kx = 0; kx < 3; ++kx) {
            #pragma unroll
            for (int ch = 0; ch < 2; ++ch) {
                // B fragments: row = tap*32 + co, co = nt*8 + g
                const unsigned* bp = sB + ((ky * 3 + kx) * 32 + g) * CELLW + ch * 8 + t;
                unsigned bh[4][2], bl[4][2];
                #pragma unroll
                for (int nt = 0; nt < 4; ++nt) {
                    const unsigned* bq = bp + nt * 8 * CELLW;
                    bh[nt][0] = bq[0];  bh[nt][1] = bq[4];
                    bl[nt][0] = bq[20]; bl[nt][1] = bq[24];
                }
                // A fragments: cell = (orow+ky)*136 + (mq*32 + mt*16 + g/g+8) + kx
                const unsigned* ap = sA + ((orow + ky) * TCOLS + mq * 32 + kx + g) * CELLW
                                        + ch * 8 + t;
                #pragma unroll
                for (int mt = 0; mt < 2; ++mt) {
                    const unsigned* aq = ap + mt * 16 * CELLW;
                    unsigned ah0 = aq[0],  ah1 = aq[8 * CELLW];
                    unsigned ah2 = aq[4],  ah3 = aq[8 * CELLW + 4];
                    unsigned al0 = aq[20], al1 = aq[8 * CELLW + 20];
                    unsigned al2 = aq[24], al3 = aq[8 * CELLW + 24];
                    #pragma unroll
                    for (int nt = 0; nt < 4; ++nt) {
                        mma_bf16(acc[mt][nt], ah0, ah1, ah2, ah3, bh[nt][0], bh[nt][1]);
                        mma_bf16(acc[mt][nt], ah0, ah1, ah2, ah3, bl[nt][0], bl[nt][1]);
                        mma_bf16(acc[mt][nt], al0, al1, al2, al3, bh[nt][0], bh[nt][1]);
                    }
                }
            }
        }
    }

    // ---- epilogue
    const int oy = oh0 + orow;
    if (oy < OH_) {
        #pragma unroll
        for (int nt = 0; nt < 4; ++nt) {
            const int co0 = nt * 8 + t * 2;
            const float bs0 = __ldg(&bias[co0]);
            const float bs1 = __ldg(&bias[co0 + 1]);
            float* o0 = out + (((size_t)b * CO_ + co0)     * OH_ + oy) * OW_;
            float* o1 = out + (((size_t)b * CO_ + co0 + 1) * OH_ + oy) * OW_;
            #pragma unroll
            for (int mt = 0; mt < 2; ++mt) {
                const int pl = px0 + mq * 32 + mt * 16 + g;
                o0[pl]     = acc[mt][nt][0] + bs0;
                o1[pl]     = acc[mt][nt][1] + bs1;
                o0[pl + 8] = acc[mt][nt][2] + bs0;
                o1[pl + 8] = acc[mt][nt][3] + bs1;
            }
        }
    }
}

extern "C" void kernel_launch(void* const* d_in, const int* in_sizes, int n_in,
                              void* d_out, int out_size)
{
    const float* x    = (const float*)d_in[0];
    const float* w    = (const float*)d_in[1];
    const float* bias = (const float*)d_in[2];
    float* out        = (float*)d_out;

    // pre-pass conversions (cheap, memory-bound)
    cvt_w<<<1, 288>>>(w);
    {
        int warps = B_ * HH * 7;               // one warp per (b,h,32w-block)
        cvt_x<<<(warps * 32 + 255) / 256, 256>>>(x);
    }

    cudaFuncSetAttribute(conv3x3_mma,
                         cudaFuncAttributeMaxDynamicSharedMemorySize, SMEM_BYTES);
    conv3x3_mma<<<B_ * YT * XT, THREADS, SMEM_BYTES>>>(bias, out);
}